// round 3
// baseline (speedup 1.0000x reference)
#include <cuda_runtime.h>

#define DIMS 2048
#define SEQ  4096

// ---------------- scratch (static device globals; no allocation) ------------
__device__ float               g_A[SEQ * DIMS];     // A = X @ W_hi^T + b
__device__ __align__(16) float g_h[2][DIMS];        // h_time t lives in g_h[t&1]
__device__ unsigned int        g_tag[128 * 32];     // per-CTA step tag, 128B stride

// ---------------- small asm helpers -----------------------------------------
__device__ __forceinline__ float tanh_fast(float x) {
    float y;
    asm("tanh.approx.f32 %0, %1;" : "=f"(y) : "f"(x));
    return y;
}
__device__ __forceinline__ void st_release(unsigned int* p, unsigned int v) {
    asm volatile("st.release.gpu.global.u32 [%0], %1;" :: "l"(p), "r"(v) : "memory");
}
__device__ __forceinline__ unsigned int ld_acquire(const unsigned int* p) {
    unsigned int v;
    asm volatile("ld.acquire.gpu.global.u32 %0, [%1];" : "=r"(v) : "l"(p) : "memory");
    return v;
}
// packed fp32x2 fma: d = a*b + d
__device__ __forceinline__ void ffma2(unsigned long long& d,
                                      unsigned long long a, unsigned long long b) {
    asm("fma.rn.f32x2 %0, %1, %2, %0;" : "+l"(d) : "l"(a), "l"(b));
}
__device__ __forceinline__ float f32x2_hsum(unsigned long long a, unsigned long long b) {
    unsigned long long s;
    asm("add.rn.f32x2 %0, %1, %2;" : "=l"(s) : "l"(a), "l"(b));
    float2 f = *reinterpret_cast<float2*>(&s);
    return f.x + f.y;
}

// ---------------- init: reset tags, seed h0 ----------------------------------
__global__ void init_kernel(const float* __restrict__ h0) {
    int i = blockIdx.x * blockDim.x + threadIdx.x;
    if (i < DIMS) g_h[0][i] = h0[i];
    if (i < 128)  g_tag[i << 5] = 0u;
}

// ---------------- phase 1: A = X @ W^T + b  (fp32 tiled GEMM) ----------------
#define BM 128
#define BN 128
#define BK 8

__global__ __launch_bounds__(256) void gemm_kernel(
    const float* __restrict__ X, const float* __restrict__ W,
    const float* __restrict__ b, float* __restrict__ A)
{
    __shared__ float Xs[BK][BM];
    __shared__ float Ws[BK][BN];

    const int tid = threadIdx.x;
    const int m0  = blockIdx.y * BM;
    const int n0  = blockIdx.x * BN;
    const int tx  = tid & 15;
    const int ty  = tid >> 4;
    const int lr  = tid >> 1;
    const int lk  = (tid & 1) * 4;

    float acc[8][8];
#pragma unroll
    for (int i = 0; i < 8; i++)
#pragma unroll
        for (int j = 0; j < 8; j++) acc[i][j] = 0.f;

    for (int k0 = 0; k0 < DIMS; k0 += BK) {
        float4 xv = *(const float4*)(X + (size_t)(m0 + lr) * DIMS + k0 + lk);
        float4 wv = *(const float4*)(W + (size_t)(n0 + lr) * DIMS + k0 + lk);
        __syncthreads();
        Xs[lk + 0][lr] = xv.x; Xs[lk + 1][lr] = xv.y;
        Xs[lk + 2][lr] = xv.z; Xs[lk + 3][lr] = xv.w;
        Ws[lk + 0][lr] = wv.x; Ws[lk + 1][lr] = wv.y;
        Ws[lk + 2][lr] = wv.z; Ws[lk + 3][lr] = wv.w;
        __syncthreads();
#pragma unroll
        for (int k = 0; k < BK; k++) {
            float xr[8], wr[8];
#pragma unroll
            for (int i = 0; i < 8; i++) xr[i] = Xs[k][ty + 16 * i];
#pragma unroll
            for (int j = 0; j < 8; j++) wr[j] = Ws[k][tx + 16 * j];
#pragma unroll
            for (int i = 0; i < 8; i++)
#pragma unroll
                for (int j = 0; j < 8; j++) acc[i][j] += xr[i] * wr[j];
        }
    }
#pragma unroll
    for (int i = 0; i < 8; i++) {
        const int m = m0 + ty + 16 * i;
#pragma unroll
        for (int j = 0; j < 8; j++) {
            const int n = n0 + tx + 16 * j;
            A[(size_t)m * DIMS + n] = acc[i][j] + b[n];
        }
    }
}

// ---------------- phase 2: persistent sequential RNN -------------------------
// Payload-coupled tags: writer CTA c publishes its 16 h floats with a single
// releasing thread; reader thread i polls ONLY tag i (128B-strided -> spread
// over many LTS partitions) and immediately pulls region i into smem.
#define NCTA 128
#define RPC  16
#define RNN_THREADS 256

// XOR swizzle on 16B-granule index: kills 4-way STS conflicts of the
// 64B-strided region stores while keeping reads conflict-free.
__device__ __forceinline__ int sw(int j) { return j ^ ((j >> 3) & 7); }

__global__ __launch_bounds__(RNN_THREADS, 1) void rnn_kernel(
    const float* __restrict__ X, const float* __restrict__ Whh,
    float* __restrict__ out)
{
    __shared__ float4 h_s[DIMS / 4];   // 8 KB, swizzled 16B granules
    __shared__ float  c_s[RPC];        // collect buffer: this CTA's 16 new h

    const int tid  = threadIdx.x;
    const int wid  = tid >> 5;
    const int lane = tid & 31;
    const int cta  = blockIdx.x;
    const int row0 = cta * RPC + wid * 2;
    const int row1 = row0 + 1;

    // W_hh slice in registers as packed f32x2 pairs (2 rows per warp).
    ulonglong2 w0[16], w1[16];
    {
        const ulonglong2* W0 = (const ulonglong2*)(Whh + (size_t)row0 * DIMS);
        const ulonglong2* W1 = (const ulonglong2*)(Whh + (size_t)row1 * DIMS);
#pragma unroll
        for (int k = 0; k < 16; k++) {
            w0[k] = W0[lane + 32 * k];
            w1[k] = W1[lane + 32 * k];
        }
    }

    for (int t = 0; t < SEQ; t++) {
        const int cur = t & 1, nxt = cur ^ 1;

        // Step-constant operands, off the h critical chain.
        float a0 = 0.f, a1 = 0.f, xr0 = 0.f, xr1 = 0.f;
        if (lane == 0) {
            a0  = g_A[(size_t)t * DIMS + row0];
            a1  = g_A[(size_t)t * DIMS + row1];
            xr0 = X[(size_t)t * DIMS + row0];
            xr1 = X[(size_t)t * DIMS + row1];
        }

        // Ingest h_prev: thread i<128 waits for region i's tag, then pulls
        // its 64B straight into (swizzled) smem. t==0: h0 pre-seeded.
        if (tid < NCTA) {
            if (t > 0) {
                while (ld_acquire(&g_tag[tid << 5]) < (unsigned)t) { }
            }
            const float4* src = (const float4*)g_h[cur] + tid * 4;
            float4 v0 = src[0], v1 = src[1], v2 = src[2], v3 = src[3];
            h_s[sw(tid * 4 + 0)] = v0;
            h_s[sw(tid * 4 + 1)] = v1;
            h_s[sw(tid * 4 + 2)] = v2;
            h_s[sw(tid * 4 + 3)] = v3;
        }
        __syncthreads();   // all regions staged

        // 2 dot products per warp; W in registers, h broadcast from smem.
        unsigned long long a0x = 0ull, a0y = 0ull, a1x = 0ull, a1y = 0ull;
#pragma unroll
        for (int k = 0; k < 16; k++) {
            ulonglong2 hv = *(const ulonglong2*)&h_s[sw(lane + 32 * k)];
            ffma2(a0x, w0[k].x, hv.x);  ffma2(a0y, w0[k].y, hv.y);
            ffma2(a1x, w1[k].x, hv.x);  ffma2(a1y, w1[k].y, hv.y);
        }
        float acc0 = f32x2_hsum(a0x, a0y);
        float acc1 = f32x2_hsum(a1x, a1y);
#pragma unroll
        for (int o = 16; o > 0; o >>= 1) {
            acc0 += __shfl_xor_sync(0xffffffffu, acc0, o);
            acc1 += __shfl_xor_sync(0xffffffffu, acc1, o);
        }

        if (lane == 0) {
            float h0n = tanh_fast(a0 + acc0);
            float h1n = tanh_fast(a1 + acc1);
            c_s[wid * 2 + 0] = h0n;
            c_s[wid * 2 + 1] = h1n;
            // residual outputs: independent of the publish chain
            out[(size_t)t * DIMS + row0] = xr0 + h0n;
            out[(size_t)t * DIMS + row1] = xr1 + h1n;
        }
        __syncthreads();   // c_s complete (also protects h_s reuse next iter)

        // Single releasing publisher: tid0 owns ALL 16 stores + the tag, so
        // st.release's same-thread ordering makes the payload visible before
        // the tag — no MEMBAR, no RED, no cross-thread ordering gap.
        if (tid == 0) {
            float4* dst = (float4*)g_h[nxt] + cta * 4;
            dst[0] = *(const float4*)&c_s[0];
            dst[1] = *(const float4*)&c_s[4];
            dst[2] = *(const float4*)&c_s[8];
            dst[3] = *(const float4*)&c_s[12];
            st_release(&g_tag[cta << 5], (unsigned)(t + 1));
        }
    }
}

// ---------------- launch ------------------------------------------------------
extern "C" void kernel_launch(void* const* d_in, const int* in_sizes, int n_in,
                              void* d_out, int out_size) {
    const float* X    = (const float*)d_in[0];  // [SEQ, DIMS]
    const float* W_hi = (const float*)d_in[1];  // [DIMS, DIMS]
    const float* W_hh = (const float*)d_in[2];  // [DIMS, DIMS]
    const float* b    = (const float*)d_in[3];  // [DIMS]
    const float* h0   = (const float*)d_in[4];  // [DIMS]
    float* out = (float*)d_out;

    float* A;
    cudaGetSymbolAddress((void**)&A, g_A);

    init_kernel<<<(DIMS + 255) / 256, 256>>>(h0);

    dim3 ggrid(DIMS / BN, SEQ / BM);            // (16, 32)
    gemm_kernel<<<ggrid, 256>>>(X, W_hi, b, A);

    rnn_kernel<<<NCTA, RNN_THREADS>>>(X, W_hh, out);
}

// round 4
// speedup vs baseline: 1.4773x; 1.4773x over previous
#include <cuda_runtime.h>

#define DIMS 2048
#define SEQ  4096
#define SENT 2.0f   // sentinel: tanh output is in (-1,1), h0 = 0 -> never 2.0

// ---------------- scratch (static device globals; no allocation) ------------
__device__ float g_A[SEQ * DIMS];                         // A = X @ W_hi^T + b
__device__ __align__(16) float g_hist[(SEQ + 1) * DIMS];  // write-once h history

// ---------------- small asm helpers -----------------------------------------
__device__ __forceinline__ float tanh_fast(float x) {
    float y;
    asm("tanh.approx.f32 %0, %1;" : "=f"(y) : "f"(x));
    return y;
}
__device__ __forceinline__ float4 ldg_vol_v4(const float4* p) {
    float4 v;
    asm volatile("ld.volatile.global.v4.f32 {%0,%1,%2,%3}, [%4];"
                 : "=f"(v.x), "=f"(v.y), "=f"(v.z), "=f"(v.w) : "l"(p));
    return v;
}
__device__ __forceinline__ void stg_vol_v4(float4* p, float4 v) {
    asm volatile("st.volatile.global.v4.f32 [%0], {%1,%2,%3,%4};"
                 :: "l"(p), "f"(v.x), "f"(v.y), "f"(v.z), "f"(v.w) : "memory");
}
// packed fp32x2 ops
__device__ __forceinline__ void ffma2(unsigned long long& d,
                                      unsigned long long a, unsigned long long b) {
    asm("fma.rn.f32x2 %0, %1, %2, %0;" : "+l"(d) : "l"(a), "l"(b));
}
__device__ __forceinline__ unsigned long long add2(unsigned long long a,
                                                   unsigned long long b) {
    unsigned long long s;
    asm("add.rn.f32x2 %0, %1, %2;" : "=l"(s) : "l"(a), "l"(b));
    return s;
}
__device__ __forceinline__ unsigned long long pack2(float x) {
    unsigned long long r;
    asm("mov.b64 %0, {%1, %1};" : "=l"(r) : "f"(x));
    return r;
}
__device__ __forceinline__ float f32x2_hsum(unsigned long long a, unsigned long long b) {
    unsigned long long s = add2(a, b);
    float2 f = *reinterpret_cast<float2*>(&s);
    return f.x + f.y;
}

// ---------------- init: poison history, seed h0 -------------------------------
__global__ void poison_kernel() {
    const float4 s = make_float4(SENT, SENT, SENT, SENT);
    float4* p = (float4*)g_hist;
    const int total = (SEQ + 1) * (DIMS / 4);
    for (int w = blockIdx.x * blockDim.x + threadIdx.x; w < total;
         w += gridDim.x * blockDim.x)
        p[w] = s;
}
__global__ void seed_kernel(const float* __restrict__ h0) {
    int i = blockIdx.x * blockDim.x + threadIdx.x;
    if (i < DIMS) g_hist[i] = h0[i];
}

// ---------------- phase 1: A = X @ W^T + b  (packed f32x2 GEMM) ---------------
#define BM 128
#define BN 128
#define BK 8

__global__ __launch_bounds__(256) void gemm_kernel(
    const float* __restrict__ X, const float* __restrict__ W,
    const float* __restrict__ b, float* __restrict__ A)
{
    __shared__ __align__(16) float Xs[BK][BM];
    __shared__ __align__(16) float Ws[BK][BN];

    const int tid = threadIdx.x;
    const int m0  = blockIdx.y * BM;
    const int n0  = blockIdx.x * BN;
    const int tx  = tid & 15;       // column pair base: tx*2 + 32*jp
    const int ty  = tid >> 4;       // row: ty + 16*i
    const int lr  = tid >> 1;
    const int lk  = (tid & 1) * 4;

    unsigned long long acc[8][4];
#pragma unroll
    for (int i = 0; i < 8; i++)
#pragma unroll
        for (int jp = 0; jp < 4; jp++) acc[i][jp] = 0ull;

    for (int k0 = 0; k0 < DIMS; k0 += BK) {
        float4 xv = *(const float4*)(X + (size_t)(m0 + lr) * DIMS + k0 + lk);
        float4 wv = *(const float4*)(W + (size_t)(n0 + lr) * DIMS + k0 + lk);
        __syncthreads();
        Xs[lk + 0][lr] = xv.x; Xs[lk + 1][lr] = xv.y;
        Xs[lk + 2][lr] = xv.z; Xs[lk + 3][lr] = xv.w;
        Ws[lk + 0][lr] = wv.x; Ws[lk + 1][lr] = wv.y;
        Ws[lk + 2][lr] = wv.z; Ws[lk + 3][lr] = wv.w;
        __syncthreads();
#pragma unroll
        for (int k = 0; k < BK; k++) {
            unsigned long long xd[8], wp[4];
#pragma unroll
            for (int i = 0; i < 8; i++) xd[i] = pack2(Xs[k][ty + 16 * i]);
#pragma unroll
            for (int jp = 0; jp < 4; jp++)
                wp[jp] = *(const unsigned long long*)&Ws[k][tx * 2 + 32 * jp];
#pragma unroll
            for (int i = 0; i < 8; i++)
#pragma unroll
                for (int jp = 0; jp < 4; jp++) ffma2(acc[i][jp], xd[i], wp[jp]);
        }
    }
    unsigned long long bp[4];
#pragma unroll
    for (int jp = 0; jp < 4; jp++)
        bp[jp] = *(const unsigned long long*)&b[n0 + tx * 2 + 32 * jp];
#pragma unroll
    for (int i = 0; i < 8; i++) {
        const int m = m0 + ty + 16 * i;
#pragma unroll
        for (int jp = 0; jp < 4; jp++) {
            *(unsigned long long*)&A[(size_t)m * DIMS + n0 + tx * 2 + 32 * jp] =
                add2(acc[i][jp], bp[jp]);
        }
    }
}

// ---------------- phase 2: persistent sequential RNN --------------------------
// Value-signaled exchange: write-once history buffer, sentinel-poison, readers
// poll payload words directly with volatile v4 loads. Zero fences, zero tags.
#define NCTA 128
#define RPC  16
#define RNN_THREADS 256

__global__ __launch_bounds__(RNN_THREADS, 1) void rnn_kernel(
    const float* __restrict__ X, const float* __restrict__ Whh,
    float* __restrict__ out)
{
    __shared__ __align__(16) float4 h_s[DIMS / 4];  // 8 KB
    __shared__ __align__(16) float  c_s[RPC];       // this CTA's 16 new h

    const int tid  = threadIdx.x;
    const int wid  = tid >> 5;
    const int lane = tid & 31;
    const int cta  = blockIdx.x;
    const int row0 = cta * RPC + wid * 2;
    const int row1 = row0 + 1;

    // W_hh slice in registers as packed f32x2 pairs (2 rows per warp).
    ulonglong2 w0[16], w1[16];
    {
        const ulonglong2* W0 = (const ulonglong2*)(Whh + (size_t)row0 * DIMS);
        const ulonglong2* W1 = (const ulonglong2*)(Whh + (size_t)row1 * DIMS);
#pragma unroll
        for (int k = 0; k < 16; k++) {
            w0[k] = W0[lane + 32 * k];
            w1[k] = W1[lane + 32 * k];
        }
    }

    for (int t = 0; t < SEQ; t++) {
        const float4* hb = (const float4*)(g_hist + (size_t)t * DIMS);
        float4*       hn = (float4*)(g_hist + (size_t)(t + 1) * DIMS);

        // Step-constant operands, off the h critical chain.
        float a0 = 0.f, a1 = 0.f, xr0 = 0.f, xr1 = 0.f;
        if (lane == 0) {
            a0  = g_A[(size_t)t * DIMS + row0];
            a1  = g_A[(size_t)t * DIMS + row1];
            xr0 = X[(size_t)t * DIMS + row0];
            xr1 = X[(size_t)t * DIMS + row1];
        }

        // Ingest h_prev: each thread owns 2 of the 512 16B words; the payload
        // IS the signal (sentinel 2.0 can never be a tanh output / h0 value).
        {
            float4 va = ldg_vol_v4(hb + tid);
            float4 vb = ldg_vol_v4(hb + tid + RNN_THREADS);
            while (va.x == SENT || va.y == SENT || va.z == SENT || va.w == SENT)
                va = ldg_vol_v4(hb + tid);
            while (vb.x == SENT || vb.y == SENT || vb.z == SENT || vb.w == SENT)
                vb = ldg_vol_v4(hb + tid + RNN_THREADS);
            h_s[tid]               = va;
            h_s[tid + RNN_THREADS] = vb;
        }
        __syncthreads();   // h_s fully staged

        // 2 dot products per warp; W in registers, h broadcast from smem,
        // packed f32x2 FMA (2 MACs / instruction).
        unsigned long long a0x = 0ull, a0y = 0ull, a1x = 0ull, a1y = 0ull;
#pragma unroll
        for (int k = 0; k < 16; k++) {
            ulonglong2 hv = *(const ulonglong2*)&h_s[lane + 32 * k];
            ffma2(a0x, w0[k].x, hv.x);  ffma2(a0y, w0[k].y, hv.y);
            ffma2(a1x, w1[k].x, hv.x);  ffma2(a1y, w1[k].y, hv.y);
        }
        float acc0 = f32x2_hsum(a0x, a0y);
        float acc1 = f32x2_hsum(a1x, a1y);
#pragma unroll
        for (int o = 16; o > 0; o >>= 1) {
            acc0 += __shfl_xor_sync(0xffffffffu, acc0, o);
            acc1 += __shfl_xor_sync(0xffffffffu, acc1, o);
        }

        if (lane == 0) {
            float h0n = tanh_fast(a0 + acc0);
            float h1n = tanh_fast(a1 + acc1);
            c_s[wid * 2 + 0] = h0n;
            c_s[wid * 2 + 1] = h1n;
            out[(size_t)t * DIMS + row0] = xr0 + h0n;   // residual, off-chain
            out[(size_t)t * DIMS + row1] = xr1 + h1n;
        }
        __syncthreads();   // c_s complete; also: all h_s reads done before reuse

        // Publish this CTA's 4 words (write-once; elements flip sentinel->value
        // independently, readers re-poll until all 4 lanes are valid).
        if (tid < 4) stg_vol_v4(hn + cta * 4 + tid, *(const float4*)&c_s[tid * 4]);
    }
}

// ---------------- launch -------------------------------------------------------
extern "C" void kernel_launch(void* const* d_in, const int* in_sizes, int n_in,
                              void* d_out, int out_size) {
    const float* X    = (const float*)d_in[0];  // [SEQ, DIMS]
    const float* W_hi = (const float*)d_in[1];  // [DIMS, DIMS]
    const float* W_hh = (const float*)d_in[2];  // [DIMS, DIMS]
    const float* b    = (const float*)d_in[3];  // [DIMS]
    const float* h0   = (const float*)d_in[4];  // [DIMS]
    float* out = (float*)d_out;

    float* A;
    cudaGetSymbolAddress((void**)&A, g_A);

    poison_kernel<<<1024, 256>>>();
    seed_kernel<<<(DIMS + 255) / 256, 256>>>(h0);

    dim3 ggrid(DIMS / BN, SEQ / BM);            // (16, 32)
    gemm_kernel<<<ggrid, 256>>>(X, W_hi, b, A);

    rnn_kernel<<<NCTA, RNN_THREADS>>>(X, W_hh, out);
}

// round 5
// speedup vs baseline: 1.4788x; 1.0010x over previous
#include <cuda_runtime.h>

#define DIMS 2048
#define SEQ  4096
#define SENT 2.0f   // sentinel: tanh output is in (-1,1), h0 = 0 -> never 2.0

// ---------------- scratch (static device globals; no allocation) ------------
__device__ float g_A[SEQ * DIMS];                         // A = X @ W_hi^T + b
__device__ __align__(16) float g_hist[(SEQ + 1) * DIMS];  // write-once h history

// ---------------- small asm helpers -----------------------------------------
__device__ __forceinline__ float tanh_fast(float x) {
    float y;
    asm("tanh.approx.f32 %0, %1;" : "=f"(y) : "f"(x));
    return y;
}
__device__ __forceinline__ float4 ldg_vol_v4(const float4* p) {
    float4 v;
    asm volatile("ld.volatile.global.v4.f32 {%0,%1,%2,%3}, [%4];"
                 : "=f"(v.x), "=f"(v.y), "=f"(v.z), "=f"(v.w) : "l"(p));
    return v;
}
__device__ __forceinline__ void stg_vol_v4(float4* p, float4 v) {
    asm volatile("st.volatile.global.v4.f32 [%0], {%1,%2,%3,%4};"
                 :: "l"(p), "f"(v.x), "f"(v.y), "f"(v.z), "f"(v.w) : "memory");
}
// packed fp32x2 ops
__device__ __forceinline__ void ffma2(unsigned long long& d,
                                      unsigned long long a, unsigned long long b) {
    asm("fma.rn.f32x2 %0, %1, %2, %0;" : "+l"(d) : "l"(a), "l"(b));
}
__device__ __forceinline__ unsigned long long add2(unsigned long long a,
                                                   unsigned long long b) {
    unsigned long long s;
    asm("add.rn.f32x2 %0, %1, %2;" : "=l"(s) : "l"(a), "l"(b));
    return s;
}
__device__ __forceinline__ unsigned long long pack2(float x) {
    unsigned long long r;
    asm("mov.b64 %0, {%1, %1};" : "=l"(r) : "f"(x));
    return r;
}
__device__ __forceinline__ float f32x2_hsum(unsigned long long a, unsigned long long b) {
    unsigned long long s = add2(a, b);
    float2 f = *reinterpret_cast<float2*>(&s);
    return f.x + f.y;
}

// ---------------- init: poison history, seed h0 -------------------------------
__global__ void poison_kernel() {
    const float4 s = make_float4(SENT, SENT, SENT, SENT);
    float4* p = (float4*)g_hist;
    const int total = (SEQ + 1) * (DIMS / 4);
    for (int w = blockIdx.x * blockDim.x + threadIdx.x; w < total;
         w += gridDim.x * blockDim.x)
        p[w] = s;
}
__global__ void seed_kernel(const float* __restrict__ h0) {
    int i = blockIdx.x * blockDim.x + threadIdx.x;
    if (i < DIMS) g_hist[i] = h0[i];
}

// ---------------- phase 1: A = X @ W^T + b  (packed f32x2 GEMM) ---------------
#define BM 128
#define BN 128
#define BK 8

__global__ __launch_bounds__(256) void gemm_kernel(
    const float* __restrict__ X, const float* __restrict__ W,
    const float* __restrict__ b, float* __restrict__ A)
{
    __shared__ __align__(16) float Xs[BK][BM];
    __shared__ __align__(16) float Ws[BK][BN];

    const int tid = threadIdx.x;
    const int m0  = blockIdx.y * BM;
    const int n0  = blockIdx.x * BN;
    const int tx  = tid & 15;       // column pair base: tx*2 + 32*jp
    const int ty  = tid >> 4;       // row: ty + 16*i
    const int lr  = tid >> 1;
    const int lk  = (tid & 1) * 4;

    unsigned long long acc[8][4];
#pragma unroll
    for (int i = 0; i < 8; i++)
#pragma unroll
        for (int jp = 0; jp < 4; jp++) acc[i][jp] = 0ull;

    for (int k0 = 0; k0 < DIMS; k0 += BK) {
        float4 xv = *(const float4*)(X + (size_t)(m0 + lr) * DIMS + k0 + lk);
        float4 wv = *(const float4*)(W + (size_t)(n0 + lr) * DIMS + k0 + lk);
        __syncthreads();
        Xs[lk + 0][lr] = xv.x; Xs[lk + 1][lr] = xv.y;
        Xs[lk + 2][lr] = xv.z; Xs[lk + 3][lr] = xv.w;
        Ws[lk + 0][lr] = wv.x; Ws[lk + 1][lr] = wv.y;
        Ws[lk + 2][lr] = wv.z; Ws[lk + 3][lr] = wv.w;
        __syncthreads();
#pragma unroll
        for (int k = 0; k < BK; k++) {
            unsigned long long xd[8], wp[4];
#pragma unroll
            for (int i = 0; i < 8; i++) xd[i] = pack2(Xs[k][ty + 16 * i]);
#pragma unroll
            for (int jp = 0; jp < 4; jp++)
                wp[jp] = *(const unsigned long long*)&Ws[k][tx * 2 + 32 * jp];
#pragma unroll
            for (int i = 0; i < 8; i++)
#pragma unroll
                for (int jp = 0; jp < 4; jp++) ffma2(acc[i][jp], xd[i], wp[jp]);
        }
    }
    unsigned long long bp[4];
#pragma unroll
    for (int jp = 0; jp < 4; jp++)
        bp[jp] = *(const unsigned long long*)&b[n0 + tx * 2 + 32 * jp];
#pragma unroll
    for (int i = 0; i < 8; i++) {
        const int m = m0 + ty + 16 * i;
#pragma unroll
        for (int jp = 0; jp < 4; jp++) {
            *(unsigned long long*)&A[(size_t)m * DIMS + n0 + tx * 2 + 32 * jp] =
                add2(acc[i][jp], bp[jp]);
        }
    }
}

// ---------------- phase 2: persistent sequential RNN --------------------------
// Value-signaled exchange: write-once history buffer, sentinel-poison, readers
// poll payload words directly with volatile v4 loads. Zero fences, zero tags.
#define NCTA 128
#define RPC  16
#define RNN_THREADS 256

__global__ __launch_bounds__(RNN_THREADS, 1) void rnn_kernel(
    const float* __restrict__ X, const float* __restrict__ Whh,
    float* __restrict__ out)
{
    __shared__ __align__(16) float4 h_s[DIMS / 4];  // 8 KB
    __shared__ __align__(16) float  c_s[RPC];       // this CTA's 16 new h

    const int tid  = threadIdx.x;
    const int wid  = tid >> 5;
    const int lane = tid & 31;
    const int cta  = blockIdx.x;
    const int row0 = cta * RPC + wid * 2;
    const int row1 = row0 + 1;

    // W_hh slice in registers as packed f32x2 pairs (2 rows per warp).
    ulonglong2 w0[16], w1[16];
    {
        const ulonglong2* W0 = (const ulonglong2*)(Whh + (size_t)row0 * DIMS);
        const ulonglong2* W1 = (const ulonglong2*)(Whh + (size_t)row1 * DIMS);
#pragma unroll
        for (int k = 0; k < 16; k++) {
            w0[k] = W0[lane + 32 * k];
            w1[k] = W1[lane + 32 * k];
        }
    }

    for (int t = 0; t < SEQ; t++) {
        const float4* hb = (const float4*)(g_hist + (size_t)t * DIMS);
        float4*       hn = (float4*)(g_hist + (size_t)(t + 1) * DIMS);

        // Step-constant operands, off the h critical chain.
        float a0 = 0.f, a1 = 0.f, xr0 = 0.f, xr1 = 0.f;
        if (lane == 0) {
            a0  = g_A[(size_t)t * DIMS + row0];
            a1  = g_A[(size_t)t * DIMS + row1];
            xr0 = X[(size_t)t * DIMS + row0];
            xr1 = X[(size_t)t * DIMS + row1];
        }

        // Ingest h_prev: each thread owns 2 of the 512 16B words; the payload
        // IS the signal (sentinel 2.0 can never be a tanh output / h0 value).
        {
            float4 va = ldg_vol_v4(hb + tid);
            float4 vb = ldg_vol_v4(hb + tid + RNN_THREADS);
            while (va.x == SENT || va.y == SENT || va.z == SENT || va.w == SENT)
                va = ldg_vol_v4(hb + tid);
            while (vb.x == SENT || vb.y == SENT || vb.z == SENT || vb.w == SENT)
                vb = ldg_vol_v4(hb + tid + RNN_THREADS);
            h_s[tid]               = va;
            h_s[tid + RNN_THREADS] = vb;
        }
        __syncthreads();   // h_s fully staged

        // 2 dot products per warp; W in registers, h broadcast from smem,
        // packed f32x2 FMA (2 MACs / instruction).
        unsigned long long a0x = 0ull, a0y = 0ull, a1x = 0ull, a1y = 0ull;
#pragma unroll
        for (int k = 0; k < 16; k++) {
            ulonglong2 hv = *(const ulonglong2*)&h_s[lane + 32 * k];
            ffma2(a0x, w0[k].x, hv.x);  ffma2(a0y, w0[k].y, hv.y);
            ffma2(a1x, w1[k].x, hv.x);  ffma2(a1y, w1[k].y, hv.y);
        }
        float acc0 = f32x2_hsum(a0x, a0y);
        float acc1 = f32x2_hsum(a1x, a1y);
#pragma unroll
        for (int o = 16; o > 0; o >>= 1) {
            acc0 += __shfl_xor_sync(0xffffffffu, acc0, o);
            acc1 += __shfl_xor_sync(0xffffffffu, acc1, o);
        }

        if (lane == 0) {
            float h0n = tanh_fast(a0 + acc0);
            float h1n = tanh_fast(a1 + acc1);
            c_s[wid * 2 + 0] = h0n;
            c_s[wid * 2 + 1] = h1n;
            out[(size_t)t * DIMS + row0] = xr0 + h0n;   // residual, off-chain
            out[(size_t)t * DIMS + row1] = xr1 + h1n;
        }
        __syncthreads();   // c_s complete; also: all h_s reads done before reuse

        // Publish this CTA's 4 words (write-once; elements flip sentinel->value
        // independently, readers re-poll until all 4 lanes are valid).
        if (tid < 4) stg_vol_v4(hn + cta * 4 + tid, *(const float4*)&c_s[tid * 4]);
    }
}

// ---------------- launch -------------------------------------------------------
extern "C" void kernel_launch(void* const* d_in, const int* in_sizes, int n_in,
                              void* d_out, int out_size) {
    const float* X    = (const float*)d_in[0];  // [SEQ, DIMS]
    const float* W_hi = (const float*)d_in[1];  // [DIMS, DIMS]
    const float* W_hh = (const float*)d_in[2];  // [DIMS, DIMS]
    const float* b    = (const float*)d_in[3];  // [DIMS]
    const float* h0   = (const float*)d_in[4];  // [DIMS]
    float* out = (float*)d_out;

    float* A;
    cudaGetSymbolAddress((void**)&A, g_A);

    poison_kernel<<<1024, 256>>>();
    seed_kernel<<<(DIMS + 255) / 256, 256>>>(h0);

    dim3 ggrid(DIMS / BN, SEQ / BM);            // (16, 32)
    gemm_kernel<<<ggrid, 256>>>(X, W_hi, b, A);

    rnn_kernel<<<NCTA, RNN_THREADS>>>(X, W_hh, out);
}